// round 2
// baseline (speedup 1.0000x reference)
#include <cuda_runtime.h>
#include <cuda_bf16.h>
#include <cstdio>

// Problem dims (fixed by the reference)
#define BATCH 4
#define SEQ   2048
#define DIM   1024
#define NHEAD 16
#define HDIM  64
#define FFD   4096
#define MROWS (BATCH*SEQ)   // 8192

// ---------------- scratch (static device globals; no runtime alloc) -------
__device__ float g_h   [(size_t)MROWS * DIM];   // ln out (reused for ln1 & ln2)
__device__ float g_q   [(size_t)MROWS * DIM];
__device__ float g_k   [(size_t)MROWS * DIM];
__device__ float g_v   [(size_t)MROWS * DIM];
__device__ float g_attn[(size_t)MROWS * DIM];
__device__ float g_x1  [(size_t)MROWS * DIM];
__device__ float g_ff  [(size_t)MROWS * FFD];

// ---------------- layernorm: one row (1024) per block, 256 threads -------
__global__ __launch_bounds__(256) void ln_kernel(
    const float* __restrict__ X, const float* __restrict__ gamma,
    const float* __restrict__ beta, float* __restrict__ Y)
{
    int row = blockIdx.x;
    const float* x = X + (size_t)row * DIM;
    float4 v = *(const float4*)(x + threadIdx.x * 4);
    float s  = v.x + v.y + v.z + v.w;
    float ss = v.x*v.x + v.y*v.y + v.z*v.z + v.w*v.w;

    #pragma unroll
    for (int o = 16; o; o >>= 1) {
        s  += __shfl_xor_sync(0xffffffffu, s, o);
        ss += __shfl_xor_sync(0xffffffffu, ss, o);
    }
    __shared__ float sw[8], ssw[8], bc[2];
    int w = threadIdx.x >> 5, lane = threadIdx.x & 31;
    if (lane == 0) { sw[w] = s; ssw[w] = ss; }
    __syncthreads();
    if (threadIdx.x == 0) {
        float S = 0.f, SS = 0.f;
        #pragma unroll
        for (int i = 0; i < 8; ++i) { S += sw[i]; SS += ssw[i]; }
        float mu  = S * (1.f / DIM);
        float var = SS * (1.f / DIM) - mu * mu;
        bc[0] = mu;
        bc[1] = rsqrtf(var + 1e-5f);
    }
    __syncthreads();
    float mu = bc[0], r = bc[1];
    float4 gv = *(const float4*)(gamma + threadIdx.x * 4);
    float4 bv = *(const float4*)(beta  + threadIdx.x * 4);
    float4 o;
    o.x = (v.x - mu) * r * gv.x + bv.x;
    o.y = (v.y - mu) * r * gv.y + bv.y;
    o.z = (v.z - mu) * r * gv.z + bv.z;
    o.w = (v.w - mu) * r * gv.w + bv.w;
    *(float4*)(Y + (size_t)row * DIM + threadIdx.x * 4) = o;
}

// ---------------- SGEMM: C[M,N] = A[M,K] @ B[K,N]  (+bias)(+res)(relu) ----
// 128x128 block tile, BK=16, 8x8 per thread, 256 threads.
template<bool HAS_BIAS, bool HAS_RES, bool RELU>
__global__ __launch_bounds__(256) void gemm_kernel(
    const float* __restrict__ A, const float* __restrict__ B,
    const float* __restrict__ bias, const float* __restrict__ Res,
    float* __restrict__ C, int M, int N, int K)
{
    constexpr int BM = 128, BN = 128, BK = 16, TM = 8, TN = 8;
    __shared__ float As[BK][BM + 4];
    __shared__ float Bs[BK][BN];

    int tid = threadIdx.x;
    int tx = tid & 15, ty = tid >> 4;
    int bm = blockIdx.y, bn = blockIdx.x;

    const float* Ablk = A + (size_t)bm * BM * K;
    const float* Bblk = B + (size_t)bn * BN;

    float acc[TM][TN] = {};
    float af[TM], bf[TN];

    for (int k0 = 0; k0 < K; k0 += BK) {
        // A tile: 128x16, transposed into As[k][row]
        #pragma unroll
        for (int it = 0; it < 2; ++it) {
            int i = tid + it * 256;
            int row = i >> 2;
            int c4  = (i & 3) << 2;
            float4 v = *(const float4*)(Ablk + (size_t)row * K + k0 + c4);
            As[c4 + 0][row] = v.x;
            As[c4 + 1][row] = v.y;
            As[c4 + 2][row] = v.z;
            As[c4 + 3][row] = v.w;
        }
        // B tile: 16x128 row-major
        #pragma unroll
        for (int it = 0; it < 2; ++it) {
            int i = tid + it * 256;
            int row = i >> 5;
            int c4  = (i & 31) << 2;
            *(float4*)&Bs[row][c4] =
                *(const float4*)(Bblk + (size_t)(k0 + row) * N + c4);
        }
        __syncthreads();

        #pragma unroll
        for (int kk = 0; kk < BK; ++kk) {
            *(float4*)&af[0] = *(const float4*)&As[kk][ty * TM];
            *(float4*)&af[4] = *(const float4*)&As[kk][ty * TM + 4];
            *(float4*)&bf[0] = *(const float4*)&Bs[kk][tx * TN];
            *(float4*)&bf[4] = *(const float4*)&Bs[kk][tx * TN + 4];
            #pragma unroll
            for (int i = 0; i < TM; ++i)
                #pragma unroll
                for (int j = 0; j < TN; ++j)
                    acc[i][j] += af[i] * bf[j];
        }
        __syncthreads();
    }

    #pragma unroll
    for (int i = 0; i < TM; ++i) {
        int row = bm * BM + ty * TM + i;
        #pragma unroll
        for (int j = 0; j < TN; j += 4) {
            int col = bn * BN + tx * TN + j;
            float4 o;
            o.x = acc[i][j];     o.y = acc[i][j + 1];
            o.z = acc[i][j + 2]; o.w = acc[i][j + 3];
            if (HAS_BIAS) {
                o.x += bias[col];     o.y += bias[col + 1];
                o.z += bias[col + 2]; o.w += bias[col + 3];
            }
            if (HAS_RES) {
                float4 r = *(const float4*)(Res + (size_t)row * N + col);
                o.x += r.x; o.y += r.y; o.z += r.z; o.w += r.w;
            }
            if (RELU) {
                o.x = fmaxf(o.x, 0.f); o.y = fmaxf(o.y, 0.f);
                o.z = fmaxf(o.z, 0.f); o.w = fmaxf(o.w, 0.f);
            }
            *(float4*)(C + (size_t)row * N + col) = o;
        }
    }
}

// ---------------- causal flash attention --------------------------------
// grid (T/64, H, B), 64 threads; thread t owns query row qt*64+t.
__global__ __launch_bounds__(64) void attn_kernel(
    const float* __restrict__ Q, const float* __restrict__ Kg,
    const float* __restrict__ Vg, float* __restrict__ O)
{
    __shared__ float Ks[64][64];
    __shared__ float Vs[64][64];
    __shared__ float Ss[64][64];   // [j][t]  (conflict-free per-lane access)

    int t  = threadIdx.x;
    int qt = blockIdx.x, h = blockIdx.y, b = blockIdx.z;
    int qi = qt * 64 + t;
    size_t qrow = ((size_t)(b * SEQ + qi)) * DIM + h * HDIM;

    float q[HDIM];
    #pragma unroll
    for (int d4 = 0; d4 < 16; ++d4) {
        float4 v = *(const float4*)(Q + qrow + d4 * 4);
        q[d4*4+0] = v.x * 0.125f;  // HD^-0.5 = 1/8
        q[d4*4+1] = v.y * 0.125f;
        q[d4*4+2] = v.z * 0.125f;
        q[d4*4+3] = v.w * 0.125f;
    }
    float acc[HDIM];
    #pragma unroll
    for (int d = 0; d < HDIM; ++d) acc[d] = 0.f;
    float m = -1e30f, l = 0.f;

    for (int kt = 0; kt <= qt; ++kt) {
        size_t krow = ((size_t)(b * SEQ + kt * 64 + t)) * DIM + h * HDIM;
        #pragma unroll
        for (int d4 = 0; d4 < 16; ++d4) {
            *(float4*)&Ks[t][d4 * 4] = *(const float4*)(Kg + krow + d4 * 4);
            *(float4*)&Vs[t][d4 * 4] = *(const float4*)(Vg + krow + d4 * 4);
        }
        __syncthreads();

        int jmax = (kt == qt) ? (t + 1) : 64;   // causal mask
        float tmax = -1e30f;
        for (int j = 0; j < 64; ++j) {
            float s;
            if (j < jmax) {
                s = 0.f;
                #pragma unroll
                for (int d4 = 0; d4 < 16; ++d4) {
                    float4 kv = *(const float4*)&Ks[j][d4 * 4];
                    s += q[d4*4+0] * kv.x + q[d4*4+1] * kv.y
                       + q[d4*4+2] * kv.z + q[d4*4+3] * kv.w;
                }
            } else {
                s = -1e30f;
            }
            Ss[j][t] = s;
            tmax = fmaxf(tmax, s);
        }
        float mnew = fmaxf(m, tmax);
        float corr = __expf(m - mnew);
        l *= corr;
        #pragma unroll
        for (int d = 0; d < HDIM; ++d) acc[d] *= corr;

        for (int j = 0; j < 64; ++j) {
            float p = __expf(Ss[j][t] - mnew);
            l += p;
            #pragma unroll
            for (int d4 = 0; d4 < 16; ++d4) {
                float4 vv = *(const float4*)&Vs[j][d4 * 4];
                acc[d4*4+0] += p * vv.x;
                acc[d4*4+1] += p * vv.y;
                acc[d4*4+2] += p * vv.z;
                acc[d4*4+3] += p * vv.w;
            }
        }
        m = mnew;
        __syncthreads();
    }

    float inv = 1.f / l;
    #pragma unroll
    for (int d4 = 0; d4 < 16; ++d4) {
        float4 o;
        o.x = acc[d4*4+0] * inv; o.y = acc[d4*4+1] * inv;
        o.z = acc[d4*4+2] * inv; o.w = acc[d4*4+3] * inv;
        *(float4*)(O + qrow + d4 * 4) = o;
    }
}

// ---------------- launch ------------------------------------------------
extern "C" void kernel_launch(void* const* d_in, const int* in_sizes, int n_in,
                              void* d_out, int out_size)
{
    const float* x     = (const float*)d_in[0];
    const float* wq    = (const float*)d_in[1];
    const float* wk    = (const float*)d_in[2];
    const float* wv    = (const float*)d_in[3];
    const float* wo    = (const float*)d_in[4];
    const float* bo    = (const float*)d_in[5];
    const float* w1    = (const float*)d_in[6];
    const float* b1    = (const float*)d_in[7];
    const float* w2    = (const float*)d_in[8];
    const float* b2    = (const float*)d_in[9];
    const float* gln1  = (const float*)d_in[10];
    const float* bln1  = (const float*)d_in[11];
    const float* gln2  = (const float*)d_in[12];
    const float* bln2  = (const float*)d_in[13];
    float* out = (float*)d_out;

    float *p_h, *p_q, *p_k, *p_v, *p_attn, *p_x1, *p_ff;
    cudaGetSymbolAddress((void**)&p_h,    g_h);
    cudaGetSymbolAddress((void**)&p_q,    g_q);
    cudaGetSymbolAddress((void**)&p_k,    g_k);
    cudaGetSymbolAddress((void**)&p_v,    g_v);
    cudaGetSymbolAddress((void**)&p_attn, g_attn);
    cudaGetSymbolAddress((void**)&p_x1,   g_x1);
    cudaGetSymbolAddress((void**)&p_ff,   g_ff);

    dim3 gD(DIM / 128, MROWS / 128);   // (8, 64)
    dim3 gF(FFD / 128, MROWS / 128);   // (32, 64)

    // 1) h = ln1(x)
    ln_kernel<<<MROWS, 256>>>(x, gln1, bln1, p_h);
    // 2) q,k,v = h @ W{q,k,v}
    gemm_kernel<false,false,false><<<gD, 256>>>(p_h, wq, nullptr, nullptr, p_q, MROWS, DIM, DIM);
    gemm_kernel<false,false,false><<<gD, 256>>>(p_h, wk, nullptr, nullptr, p_k, MROWS, DIM, DIM);
    gemm_kernel<false,false,false><<<gD, 256>>>(p_h, wv, nullptr, nullptr, p_v, MROWS, DIM, DIM);
    // 3) causal attention
    attn_kernel<<<dim3(SEQ / 64, NHEAD, BATCH), 64>>>(p_q, p_k, p_v, p_attn);
    // 4) x1 = x + attn @ wo + bo
    gemm_kernel<true,true,false><<<gD, 256>>>(p_attn, wo, bo, x, p_x1, MROWS, DIM, DIM);
    // 5) h = ln2(x1)
    ln_kernel<<<MROWS, 256>>>(p_x1, gln2, bln2, p_h);
    // 6) ff = relu(h @ w1 + b1)
    gemm_kernel<true,false,true><<<gF, 256>>>(p_h, w1, b1, nullptr, p_ff, MROWS, FFD, DIM);
    // 7) out = x1 + ff @ w2 + b2
    gemm_kernel<true,true,false><<<gD, 256>>>(p_ff, w2, b2, p_x1, out, MROWS, DIM, FFD);
}

// round 3
// speedup vs baseline: 1.8320x; 1.8320x over previous
#include <cuda_runtime.h>
#include <cuda_bf16.h>
#include <cstdio>

// Problem dims (fixed by the reference)
#define BATCH 4
#define SEQ   2048
#define DIM   1024
#define NHEAD 16
#define HDIM  64
#define FFD   4096
#define MROWS (BATCH*SEQ)   // 8192

// ---------------- scratch (static device globals; no runtime alloc) -------
__device__ float g_h   [(size_t)MROWS * DIM];
__device__ float g_q   [(size_t)MROWS * DIM];
__device__ float g_k   [(size_t)MROWS * DIM];
__device__ float g_v   [(size_t)MROWS * DIM];
__device__ float g_attn[(size_t)MROWS * DIM];
__device__ float g_x1  [(size_t)MROWS * DIM];
__device__ float g_ff  [(size_t)MROWS * FFD];

// ---------------- helpers: tf32 + packed f32x2 ---------------------------
__device__ __forceinline__ unsigned f2tf32(float f) {
    unsigned u;
    asm("cvt.rna.tf32.f32 %0, %1;" : "=r"(u) : "f"(f));
    return u;
}

typedef unsigned long long ull_t;

__device__ __forceinline__ ull_t pack2(float x, float y) {
    ull_t d;
    asm("mov.b64 %0, {%1, %2};" : "=l"(d) : "f"(x), "f"(y));
    return d;
}
__device__ __forceinline__ void unpack2(ull_t d, float& x, float& y) {
    asm("mov.b64 {%0, %1}, %2;" : "=f"(x), "=f"(y) : "l"(d));
}
__device__ __forceinline__ ull_t ffma2(ull_t a, ull_t b, ull_t c) {
    ull_t d;
    asm("fma.rn.f32x2 %0, %1, %2, %3;" : "=l"(d) : "l"(a), "l"(b), "l"(c));
    return d;
}
__device__ __forceinline__ ull_t fmul2(ull_t a, ull_t b) {
    ull_t d;
    asm("mul.rn.f32x2 %0, %1, %2;" : "=l"(d) : "l"(a), "l"(b));
    return d;
}

__device__ __forceinline__ void mma_tf32(float* c, const unsigned* a, const unsigned* b) {
    asm volatile(
        "mma.sync.aligned.m16n8k8.row.col.f32.tf32.tf32.f32 "
        "{%0,%1,%2,%3}, {%4,%5,%6,%7}, {%8,%9}, {%0,%1,%2,%3};"
        : "+f"(c[0]), "+f"(c[1]), "+f"(c[2]), "+f"(c[3])
        : "r"(a[0]), "r"(a[1]), "r"(a[2]), "r"(a[3]), "r"(b[0]), "r"(b[1]));
}

// ---------------- layernorm: one row (1024) per block, 256 threads -------
__global__ __launch_bounds__(256) void ln_kernel(
    const float* __restrict__ X, const float* __restrict__ gamma,
    const float* __restrict__ beta, float* __restrict__ Y)
{
    int row = blockIdx.x;
    const float* x = X + (size_t)row * DIM;
    float4 v = *(const float4*)(x + threadIdx.x * 4);
    float s  = v.x + v.y + v.z + v.w;
    float ss = v.x*v.x + v.y*v.y + v.z*v.z + v.w*v.w;

    #pragma unroll
    for (int o = 16; o; o >>= 1) {
        s  += __shfl_xor_sync(0xffffffffu, s, o);
        ss += __shfl_xor_sync(0xffffffffu, ss, o);
    }
    __shared__ float sw[8], ssw[8], bc[2];
    int w = threadIdx.x >> 5, lane = threadIdx.x & 31;
    if (lane == 0) { sw[w] = s; ssw[w] = ss; }
    __syncthreads();
    if (threadIdx.x == 0) {
        float S = 0.f, SS = 0.f;
        #pragma unroll
        for (int i = 0; i < 8; ++i) { S += sw[i]; SS += ssw[i]; }
        float mu  = S * (1.f / DIM);
        float var = SS * (1.f / DIM) - mu * mu;
        bc[0] = mu;
        bc[1] = rsqrtf(var + 1e-5f);
    }
    __syncthreads();
    float mu = bc[0], r = bc[1];
    float4 gv = *(const float4*)(gamma + threadIdx.x * 4);
    float4 bv = *(const float4*)(beta  + threadIdx.x * 4);
    float4 o;
    o.x = (v.x - mu) * r * gv.x + bv.x;
    o.y = (v.y - mu) * r * gv.y + bv.y;
    o.z = (v.z - mu) * r * gv.z + bv.z;
    o.w = (v.w - mu) * r * gv.w + bv.w;
    *(float4*)(Y + (size_t)row * DIM + threadIdx.x * 4) = o;
}

// ---------------- TF32 tensor-core GEMM ----------------------------------
// C[M,N] = A[M,K] @ B[K,N] (+bias)(+res)(relu)
// 128x128 block tile, BK=16, 256 threads = 8 warps (2x4), warp tile 64x32,
// mma.m16n8k8 tf32: 4x4 mma tiles per warp, 2 k-steps per BK tile.
template<bool HAS_BIAS, bool HAS_RES, bool RELU>
__global__ __launch_bounds__(256) void gemm_tc(
    const float* __restrict__ A, const float* __restrict__ B,
    const float* __restrict__ bias, const float* __restrict__ Res,
    float* __restrict__ C, int M, int N, int K)
{
    constexpr int BM = 128, BN = 128, BK = 16;
    constexpr int AP = 20;    // As row stride (pad 4) -> conflict-free frag loads
    constexpr int BP = 136;   // Bs row stride (pad 8) -> conflict-free frag loads
    __shared__ unsigned As[BM][AP];   // tf32 bits, [m][k]
    __shared__ unsigned Bs[BK][BP];   // tf32 bits, [k][n]

    int tid  = threadIdx.x;
    int warp = tid >> 5, lane = tid & 31;
    int wm = (warp >> 2) * 64;     // warp row offset (0 or 64)
    int wn = (warp & 3) * 32;      // warp col offset (0,32,64,96)
    int lg = lane >> 2;            // group id 0..7
    int lt = lane & 3;             // thread-in-group 0..3
    int bm = blockIdx.y, bn = blockIdx.x;

    const float* Ablk = A + (size_t)bm * BM * K;
    const float* Bblk = B + (size_t)bn * BN;

    float acc[4][4][4] = {};   // [mi][ni][frag]

    for (int k0 = 0; k0 < K; k0 += BK) {
        // A tile 128x16: 512 float4 loads over 2 iterations
        #pragma unroll
        for (int it = 0; it < 2; ++it) {
            int i = tid + it * 256;
            int row = i >> 2, c4 = (i & 3) << 2;
            float4 v = *(const float4*)(Ablk + (size_t)row * K + k0 + c4);
            uint4 u;
            u.x = f2tf32(v.x); u.y = f2tf32(v.y);
            u.z = f2tf32(v.z); u.w = f2tf32(v.w);
            *(uint4*)&As[row][c4] = u;
        }
        // B tile 16x128
        #pragma unroll
        for (int it = 0; it < 2; ++it) {
            int i = tid + it * 256;
            int row = i >> 5, c4 = (i & 31) << 2;
            float4 v = *(const float4*)(Bblk + (size_t)(k0 + row) * N + c4);
            uint4 u;
            u.x = f2tf32(v.x); u.y = f2tf32(v.y);
            u.z = f2tf32(v.z); u.w = f2tf32(v.w);
            *(uint4*)&Bs[row][c4] = u;
        }
        __syncthreads();

        #pragma unroll
        for (int ks = 0; ks < 2; ++ks) {
            int kb = ks * 8;
            unsigned a[4][4], b[4][2];
            #pragma unroll
            for (int mi = 0; mi < 4; ++mi) {
                int r = wm + mi * 16 + lg;
                a[mi][0] = As[r    ][kb + lt];
                a[mi][1] = As[r + 8][kb + lt];
                a[mi][2] = As[r    ][kb + lt + 4];
                a[mi][3] = As[r + 8][kb + lt + 4];
            }
            #pragma unroll
            for (int ni = 0; ni < 4; ++ni) {
                int c = wn + ni * 8 + lg;
                b[ni][0] = Bs[kb + lt    ][c];
                b[ni][1] = Bs[kb + lt + 4][c];
            }
            #pragma unroll
            for (int mi = 0; mi < 4; ++mi)
                #pragma unroll
                for (int ni = 0; ni < 4; ++ni)
                    mma_tf32(acc[mi][ni], a[mi], b[ni]);
        }
        __syncthreads();
    }

    // epilogue: c0,c1 @ (row, col..col+1); c2,c3 @ (row+8, col..col+1)
    #pragma unroll
    for (int mi = 0; mi < 4; ++mi) {
        int r0 = bm * BM + wm + mi * 16 + lg;
        #pragma unroll
        for (int ni = 0; ni < 4; ++ni) {
            int c0 = bn * BN + wn + ni * 8 + lt * 2;
            #pragma unroll
            for (int half = 0; half < 2; ++half) {
                int row = r0 + half * 8;
                float2 o;
                o.x = acc[mi][ni][half * 2 + 0];
                o.y = acc[mi][ni][half * 2 + 1];
                if (HAS_BIAS) { o.x += bias[c0]; o.y += bias[c0 + 1]; }
                if (HAS_RES) {
                    float2 rr = *(const float2*)(Res + (size_t)row * N + c0);
                    o.x += rr.x; o.y += rr.y;
                }
                if (RELU) { o.x = fmaxf(o.x, 0.f); o.y = fmaxf(o.y, 0.f); }
                *(float2*)(C + (size_t)row * N + c0) = o;
            }
        }
    }
}

// ---------------- causal flash attention (packed f32x2 math) -------------
// grid (T/64, H, B), 64 threads; thread t owns query row qt*64+t.
__global__ __launch_bounds__(64) void attn_kernel(
    const float* __restrict__ Q, const float* __restrict__ Kg,
    const float* __restrict__ Vg, float* __restrict__ O)
{
    __shared__ float Ks[64][64];
    __shared__ float Vs[64][64];
    __shared__ float Ss[64][64];   // [j][t]

    int t  = threadIdx.x;
    int qt = blockIdx.x, h = blockIdx.y, b = blockIdx.z;
    int qi = qt * 64 + t;
    size_t qrow = ((size_t)(b * SEQ + qi)) * DIM + h * HDIM;

    // q as 32 packed f32x2 pairs, pre-scaled by 1/8
    ull_t q2[32];
    #pragma unroll
    for (int d4 = 0; d4 < 16; ++d4) {
        float4 v = *(const float4*)(Q + qrow + d4 * 4);
        q2[d4 * 2 + 0] = pack2(v.x * 0.125f, v.y * 0.125f);
        q2[d4 * 2 + 1] = pack2(v.z * 0.125f, v.w * 0.125f);
    }
    ull_t acc2[32];
    #pragma unroll
    for (int d = 0; d < 32; ++d) acc2[d] = 0ull;   // bits of (0.f,0.f)
    float m = -1e30f, l = 0.f;

    for (int kt = 0; kt <= qt; ++kt) {
        size_t krow = ((size_t)(b * SEQ + kt * 64 + t)) * DIM + h * HDIM;
        #pragma unroll
        for (int d4 = 0; d4 < 16; ++d4) {
            *(float4*)&Ks[t][d4 * 4] = *(const float4*)(Kg + krow + d4 * 4);
            *(float4*)&Vs[t][d4 * 4] = *(const float4*)(Vg + krow + d4 * 4);
        }
        __syncthreads();

        int jmax = (kt == qt) ? (t + 1) : 64;   // causal mask
        float tmax = -1e30f;
        for (int j = 0; j < 64; ++j) {
            float s;
            if (j < jmax) {
                ull_t s2 = 0ull;
                const ulonglong2* kp = (const ulonglong2*)&Ks[j][0];
                #pragma unroll
                for (int p = 0; p < 16; ++p) {
                    ulonglong2 kk = kp[p];
                    s2 = ffma2(q2[p * 2 + 0], kk.x, s2);
                    s2 = ffma2(q2[p * 2 + 1], kk.y, s2);
                }
                float sx, sy; unpack2(s2, sx, sy);
                s = sx + sy;
            } else {
                s = -1e30f;
            }
            Ss[j][t] = s;
            tmax = fmaxf(tmax, s);
        }
        float mnew = fmaxf(m, tmax);
        float corr = __expf(m - mnew);
        l *= corr;
        ull_t c2 = pack2(corr, corr);
        #pragma unroll
        for (int d = 0; d < 32; ++d) acc2[d] = fmul2(acc2[d], c2);

        for (int j = 0; j < 64; ++j) {
            float p = __expf(Ss[j][t] - mnew);
            l += p;
            ull_t pp = pack2(p, p);
            const ulonglong2* vp = (const ulonglong2*)&Vs[j][0];
            #pragma unroll
            for (int d = 0; d < 16; ++d) {
                ulonglong2 vv = vp[d];
                acc2[d * 2 + 0] = ffma2(pp, vv.x, acc2[d * 2 + 0]);
                acc2[d * 2 + 1] = ffma2(pp, vv.y, acc2[d * 2 + 1]);
            }
        }
        m = mnew;
        __syncthreads();
    }

    float inv = 1.f / l;
    #pragma unroll
    for (int d = 0; d < 32; ++d) {
        float x, y; unpack2(acc2[d], x, y);
        float2 o; o.x = x * inv; o.y = y * inv;
        *(float2*)(O + qrow + d * 2) = o;
    }
}

// ---------------- launch ------------------------------------------------
extern "C" void kernel_launch(void* const* d_in, const int* in_sizes, int n_in,
                              void* d_out, int out_size)
{
    const float* x     = (const float*)d_in[0];
    const float* wq    = (const float*)d_in[1];
    const float* wk    = (const float*)d_in[2];
    const float* wv    = (const float*)d_in[3];
    const float* wo    = (const float*)d_in[4];
    const float* bo    = (const float*)d_in[5];
    const float* w1    = (const float*)d_in[6];
    const float* b1    = (const float*)d_in[7];
    const float* w2    = (const float*)d_in[8];
    const float* b2    = (const float*)d_in[9];
    const float* gln1  = (const float*)d_in[10];
    const float* bln1  = (const float*)d_in[11];
    const float* gln2  = (const float*)d_in[12];
    const float* bln2  = (const float*)d_in[13];
    float* out = (float*)d_out;

    float *p_h, *p_q, *p_k, *p_v, *p_attn, *p_x1, *p_ff;
    cudaGetSymbolAddress((void**)&p_h,    g_h);
    cudaGetSymbolAddress((void**)&p_q,    g_q);
    cudaGetSymbolAddress((void**)&p_k,    g_k);
    cudaGetSymbolAddress((void**)&p_v,    g_v);
    cudaGetSymbolAddress((void**)&p_attn, g_attn);
    cudaGetSymbolAddress((void**)&p_x1,   g_x1);
    cudaGetSymbolAddress((void**)&p_ff,   g_ff);

    dim3 gD(DIM / 128, MROWS / 128);   // (8, 64)
    dim3 gF(FFD / 128, MROWS / 128);   // (32, 64)

    // 1) h = ln1(x)
    ln_kernel<<<MROWS, 256>>>(x, gln1, bln1, p_h);
    // 2) q,k,v = h @ W{q,k,v}
    gemm_tc<false,false,false><<<gD, 256>>>(p_h, wq, nullptr, nullptr, p_q, MROWS, DIM, DIM);
    gemm_tc<false,false,false><<<gD, 256>>>(p_h, wk, nullptr, nullptr, p_k, MROWS, DIM, DIM);
    gemm_tc<false,false,false><<<gD, 256>>>(p_h, wv, nullptr, nullptr, p_v, MROWS, DIM, DIM);
    // 3) causal attention
    attn_kernel<<<dim3(SEQ / 64, NHEAD, BATCH), 64>>>(p_q, p_k, p_v, p_attn);
    // 4) x1 = x + attn @ wo + bo
    gemm_tc<true,true,false><<<gD, 256>>>(p_attn, wo, bo, x, p_x1, MROWS, DIM, DIM);
    // 5) h = ln2(x1)
    ln_kernel<<<MROWS, 256>>>(p_x1, gln2, bln2, p_h);
    // 6) ff = relu(h @ w1 + b1)
    gemm_tc<true,false,true><<<gF, 256>>>(p_h, w1, b1, nullptr, p_ff, MROWS, FFD, DIM);
    // 7) out = x1 + ff @ w2 + b2
    gemm_tc<true,true,false><<<gD, 256>>>(p_ff, w2, b2, p_x1, out, MROWS, DIM, FFD);
}

// round 4
// speedup vs baseline: 3.4790x; 1.8990x over previous
#include <cuda_runtime.h>
#include <cuda_bf16.h>
#include <cstdio>

// Problem dims (fixed by the reference)
#define BATCH 4
#define SEQ   2048
#define DIM   1024
#define NHEAD 16
#define HDIM  64
#define FFD   4096
#define MROWS (BATCH*SEQ)   // 8192

// ---------------- scratch (static device globals; no runtime alloc) -------
__device__ float g_h   [(size_t)MROWS * DIM];
__device__ float g_q   [(size_t)MROWS * DIM];
__device__ float g_k   [(size_t)MROWS * DIM];
__device__ float g_v   [(size_t)MROWS * DIM];
__device__ float g_attn[(size_t)MROWS * DIM];
__device__ float g_x1  [(size_t)MROWS * DIM];
__device__ float g_ff  [(size_t)MROWS * FFD];

// ---------------- helpers -------------------------------------------------
__device__ __forceinline__ unsigned f2tf32(float f) {
    unsigned u;
    asm("cvt.rna.tf32.f32 %0, %1;" : "=r"(u) : "f"(f));
    return u;
}

__device__ __forceinline__ void mma_tf32(float* c, const unsigned* a, const unsigned* b) {
    asm volatile(
        "mma.sync.aligned.m16n8k8.row.col.f32.tf32.tf32.f32 "
        "{%0,%1,%2,%3}, {%4,%5,%6,%7}, {%8,%9}, {%0,%1,%2,%3};"
        : "+f"(c[0]), "+f"(c[1]), "+f"(c[2]), "+f"(c[3])
        : "r"(a[0]), "r"(a[1]), "r"(a[2]), "r"(a[3]), "r"(b[0]), "r"(b[1]));
}

__device__ __forceinline__ void cpasync16(void* smem, const void* gmem) {
    unsigned s = (unsigned)__cvta_generic_to_shared(smem);
    asm volatile("cp.async.ca.shared.global [%0], [%1], 16;" :: "r"(s), "l"(gmem));
}
template<int N> __device__ __forceinline__ void cpwait() {
    asm volatile("cp.async.wait_group %0;" :: "n"(N));
}

// ---------------- layernorm: one row (1024) per block, 256 threads -------
__global__ __launch_bounds__(256) void ln_kernel(
    const float* __restrict__ X, const float* __restrict__ gamma,
    const float* __restrict__ beta, float* __restrict__ Y)
{
    int row = blockIdx.x;
    const float* x = X + (size_t)row * DIM;
    float4 v = *(const float4*)(x + threadIdx.x * 4);
    float s  = v.x + v.y + v.z + v.w;
    float ss = v.x*v.x + v.y*v.y + v.z*v.z + v.w*v.w;

    #pragma unroll
    for (int o = 16; o; o >>= 1) {
        s  += __shfl_xor_sync(0xffffffffu, s, o);
        ss += __shfl_xor_sync(0xffffffffu, ss, o);
    }
    __shared__ float sw[8], ssw[8], bc[2];
    int w = threadIdx.x >> 5, lane = threadIdx.x & 31;
    if (lane == 0) { sw[w] = s; ssw[w] = ss; }
    __syncthreads();
    if (threadIdx.x == 0) {
        float S = 0.f, SS = 0.f;
        #pragma unroll
        for (int i = 0; i < 8; ++i) { S += sw[i]; SS += ssw[i]; }
        float mu  = S * (1.f / DIM);
        float var = SS * (1.f / DIM) - mu * mu;
        bc[0] = mu;
        bc[1] = rsqrtf(var + 1e-5f);
    }
    __syncthreads();
    float mu = bc[0], r = bc[1];
    float4 gv = *(const float4*)(gamma + threadIdx.x * 4);
    float4 bv = *(const float4*)(beta  + threadIdx.x * 4);
    float4 o;
    o.x = (v.x - mu) * r * gv.x + bv.x;
    o.y = (v.y - mu) * r * gv.y + bv.y;
    o.z = (v.z - mu) * r * gv.z + bv.z;
    o.w = (v.w - mu) * r * gv.w + bv.w;
    *(float4*)(Y + (size_t)row * DIM + threadIdx.x * 4) = o;
}

// ---------------- TF32 tensor-core GEMM, cp.async double-buffered ---------
// C[M,N] = A[M,K] @ B[K,N] (+bias)(+res)(relu)
// 128x128 block tile, BK=16, 256 threads = 8 warps (2x4), warp tile 64x32.
constexpr int GAP = 20;    // As row stride (floats) — conflict-free frags
constexpr int GBP = 136;   // Bs row stride

__device__ __forceinline__ void gemm_load_tile(
    float (*As)[GAP], float (*Bs)[GBP],
    const float* Ablk, const float* Bblk, int k0, int N, int K, int tid)
{
    #pragma unroll
    for (int it = 0; it < 2; ++it) {
        int i = tid + it * 256;
        int r = i >> 2, c4 = (i & 3) << 2;
        cpasync16(&As[r][c4], Ablk + (size_t)r * K + k0 + c4);
    }
    #pragma unroll
    for (int it = 0; it < 2; ++it) {
        int i = tid + it * 256;
        int r = i >> 5, c4 = (i & 31) << 2;
        cpasync16(&Bs[r][c4], Bblk + (size_t)(k0 + r) * N + c4);
    }
    asm volatile("cp.async.commit_group;");
}

template<bool HAS_BIAS, bool HAS_RES, bool RELU>
__global__ __launch_bounds__(256) void gemm_tc(
    const float* __restrict__ A, const float* __restrict__ B,
    const float* __restrict__ bias, const float* __restrict__ Res,
    float* __restrict__ C, int M, int N, int K)
{
    constexpr int BM = 128, BN = 128, BK = 16;
    __shared__ float As[2][BM][GAP];
    __shared__ float Bs[2][BK][GBP];

    int tid  = threadIdx.x;
    int warp = tid >> 5, lane = tid & 31;
    int wm = (warp >> 2) * 64;
    int wn = (warp & 3) * 32;
    int lg = lane >> 2;
    int lt = lane & 3;
    int bm = blockIdx.y, bn = blockIdx.x;

    const float* Ablk = A + (size_t)bm * BM * K;
    const float* Bblk = B + (size_t)bn * BN;

    float acc[4][4][4] = {};

    gemm_load_tile(As[0], Bs[0], Ablk, Bblk, 0, N, K, tid);
    int T = K / BK;
    for (int t = 0; t < T; ++t) {
        if (t + 1 < T) {
            gemm_load_tile(As[(t + 1) & 1], Bs[(t + 1) & 1],
                           Ablk, Bblk, (t + 1) * BK, N, K, tid);
            cpwait<1>();
        } else {
            cpwait<0>();
        }
        __syncthreads();
        const float (*as)[GAP] = As[t & 1];
        const float (*bs)[GBP] = Bs[t & 1];

        #pragma unroll
        for (int ks = 0; ks < 2; ++ks) {
            int kb = ks * 8;
            unsigned a[4][4], b[4][2];
            #pragma unroll
            for (int mi = 0; mi < 4; ++mi) {
                int r = wm + mi * 16 + lg;
                a[mi][0] = f2tf32(as[r    ][kb + lt]);
                a[mi][1] = f2tf32(as[r + 8][kb + lt]);
                a[mi][2] = f2tf32(as[r    ][kb + lt + 4]);
                a[mi][3] = f2tf32(as[r + 8][kb + lt + 4]);
            }
            #pragma unroll
            for (int ni = 0; ni < 4; ++ni) {
                int c = wn + ni * 8 + lg;
                b[ni][0] = f2tf32(bs[kb + lt    ][c]);
                b[ni][1] = f2tf32(bs[kb + lt + 4][c]);
            }
            #pragma unroll
            for (int mi = 0; mi < 4; ++mi)
                #pragma unroll
                for (int ni = 0; ni < 4; ++ni)
                    mma_tf32(acc[mi][ni], a[mi], b[ni]);
        }
        __syncthreads();
    }

    #pragma unroll
    for (int mi = 0; mi < 4; ++mi) {
        int r0 = bm * BM + wm + mi * 16 + lg;
        #pragma unroll
        for (int ni = 0; ni < 4; ++ni) {
            int c0 = bn * BN + wn + ni * 8 + lt * 2;
            #pragma unroll
            for (int half = 0; half < 2; ++half) {
                int row = r0 + half * 8;
                float2 o;
                o.x = acc[mi][ni][half * 2 + 0];
                o.y = acc[mi][ni][half * 2 + 1];
                if (HAS_BIAS) { o.x += bias[c0]; o.y += bias[c0 + 1]; }
                if (HAS_RES) {
                    float2 rr = *(const float2*)(Res + (size_t)row * N + c0);
                    o.x += rr.x; o.y += rr.y;
                }
                if (RELU) { o.x = fmaxf(o.x, 0.f); o.y = fmaxf(o.y, 0.f); }
                *(float2*)(C + (size_t)row * N + c0) = o;
            }
        }
    }
}

// ---------------- tensor-core causal flash attention ----------------------
// grid (SEQ/64, H, B), 128 threads = 4 warps; warp w owns query rows
// [w*16, w*16+16) of a 64-query tile. S = Q K^T and O += P V via
// mma.m16n8k8 tf32. KPs holds K during the S phase, then P (per-warp rows).
__global__ __launch_bounds__(128) void attn_tc(
    const float* __restrict__ Q, const float* __restrict__ Kg,
    const float* __restrict__ Vg, float* __restrict__ O)
{
    __shared__ unsigned KPs[64][68];   // K tile (tf32), then P tile
    __shared__ unsigned Vs [64][72];   // V tile (tf32)

    int tid = threadIdx.x;
    int w = tid >> 5, lane = tid & 31;
    int lg = lane >> 2, lt = lane & 3;
    int qt = blockIdx.x, h = blockIdx.y, b = blockIdx.z;
    size_t base = ((size_t)b * SEQ) * DIM + h * HDIM;

    // ---- stage Q tile (scaled by 1/8, tf32) into KPs, grab A-fragments ----
    {
        int f = tid & 15;          // float4 index in row
        int rsub = tid >> 4;       // 0..7
        #pragma unroll
        for (int pass = 0; pass < 8; ++pass) {
            int row = pass * 8 + rsub;
            float4 v = *(const float4*)(Q + base + (size_t)(qt * 64 + row) * DIM + f * 4);
            uint4 u;
            u.x = f2tf32(v.x * 0.125f); u.y = f2tf32(v.y * 0.125f);
            u.z = f2tf32(v.z * 0.125f); u.w = f2tf32(v.w * 0.125f);
            *(uint4*)&KPs[row][f * 4] = u;
        }
    }
    __syncthreads();
    unsigned qa[8][4];
    {
        int r0 = w * 16 + lg;
        #pragma unroll
        for (int ks = 0; ks < 8; ++ks) {
            int kb = ks * 8;
            qa[ks][0] = KPs[r0    ][kb + lt];
            qa[ks][1] = KPs[r0 + 8][kb + lt];
            qa[ks][2] = KPs[r0    ][kb + lt + 4];
            qa[ks][3] = KPs[r0 + 8][kb + lt + 4];
        }
    }
    __syncthreads();

    float m0 = -1e30f, m1 = -1e30f, l0 = 0.f, l1 = 0.f;
    float oacc[8][4] = {};

    for (int kt = 0; kt <= qt; ++kt) {
        // ---- load K,V tiles (coalesced rows), convert to tf32 ----
        {
            int f = tid & 15;
            int rsub = tid >> 4;
            #pragma unroll
            for (int pass = 0; pass < 8; ++pass) {
                int row = pass * 8 + rsub;
                size_t g = base + (size_t)(kt * 64 + row) * DIM + f * 4;
                float4 kv = *(const float4*)(Kg + g);
                uint4 ku;
                ku.x = f2tf32(kv.x); ku.y = f2tf32(kv.y);
                ku.z = f2tf32(kv.z); ku.w = f2tf32(kv.w);
                *(uint4*)&KPs[row][f * 4] = ku;
                float4 vv = *(const float4*)(Vg + g);
                uint4 vu;
                vu.x = f2tf32(vv.x); vu.y = f2tf32(vv.y);
                vu.z = f2tf32(vv.z); vu.w = f2tf32(vv.w);
                *(uint4*)&Vs[row][f * 4] = vu;
            }
        }
        __syncthreads();

        // ---- S = Q K^T  (16x64 per warp) ----
        float sacc[8][4] = {};
        #pragma unroll
        for (int ks = 0; ks < 8; ++ks) {
            int kb = ks * 8;
            unsigned bf[8][2];
            #pragma unroll
            for (int ni = 0; ni < 8; ++ni) {
                bf[ni][0] = KPs[ni * 8 + lg][kb + lt];
                bf[ni][1] = KPs[ni * 8 + lg][kb + lt + 4];
            }
            #pragma unroll
            for (int ni = 0; ni < 8; ++ni)
                mma_tf32(sacc[ni], qa[ks], bf[ni]);
        }

        // ---- causal mask (diagonal tile only) ----
        if (kt == qt) {
            int rq0 = w * 16 + lg, rq1 = rq0 + 8;
            #pragma unroll
            for (int ni = 0; ni < 8; ++ni) {
                int j0 = ni * 8 + 2 * lt, j1 = j0 + 1;
                if (j0 > rq0) sacc[ni][0] = -1e30f;
                if (j1 > rq0) sacc[ni][1] = -1e30f;
                if (j0 > rq1) sacc[ni][2] = -1e30f;
                if (j1 > rq1) sacc[ni][3] = -1e30f;
            }
        }

        // ---- online softmax ----
        float mx0 = -1e30f, mx1 = -1e30f;
        #pragma unroll
        for (int ni = 0; ni < 8; ++ni) {
            mx0 = fmaxf(mx0, fmaxf(sacc[ni][0], sacc[ni][1]));
            mx1 = fmaxf(mx1, fmaxf(sacc[ni][2], sacc[ni][3]));
        }
        mx0 = fmaxf(mx0, __shfl_xor_sync(0xffffffffu, mx0, 1));
        mx0 = fmaxf(mx0, __shfl_xor_sync(0xffffffffu, mx0, 2));
        mx1 = fmaxf(mx1, __shfl_xor_sync(0xffffffffu, mx1, 1));
        mx1 = fmaxf(mx1, __shfl_xor_sync(0xffffffffu, mx1, 2));
        float m0n = fmaxf(m0, mx0), m1n = fmaxf(m1, mx1);
        float c0 = __expf(m0 - m0n), c1 = __expf(m1 - m1n);
        l0 *= c0; l1 *= c1;
        #pragma unroll
        for (int ni = 0; ni < 8; ++ni) {
            oacc[ni][0] *= c0; oacc[ni][1] *= c0;
            oacc[ni][2] *= c1; oacc[ni][3] *= c1;
        }
        m0 = m0n; m1 = m1n;

        // ---- P = exp(S-m); store into KPs (K no longer needed) ----
        __syncthreads();   // all warps done reading K
        {
            int r0 = w * 16 + lg;
            float ps0 = 0.f, ps1 = 0.f;
            #pragma unroll
            for (int ni = 0; ni < 8; ++ni) {
                float p00 = __expf(sacc[ni][0] - m0n);
                float p01 = __expf(sacc[ni][1] - m0n);
                float p10 = __expf(sacc[ni][2] - m1n);
                float p11 = __expf(sacc[ni][3] - m1n);
                ps0 += p00 + p01; ps1 += p10 + p11;
                uint2 u0; u0.x = f2tf32(p00); u0.y = f2tf32(p01);
                uint2 u1; u1.x = f2tf32(p10); u1.y = f2tf32(p11);
                *(uint2*)&KPs[r0    ][ni * 8 + 2 * lt] = u0;
                *(uint2*)&KPs[r0 + 8][ni * 8 + 2 * lt] = u1;
            }
            l0 += ps0; l1 += ps1;
        }
        __syncwarp();   // P rows are private to this warp

        // ---- O += P V ----
        #pragma unroll
        for (int ks = 0; ks < 8; ++ks) {
            int kb = ks * 8;
            int r0 = w * 16 + lg;
            unsigned pa[4];
            pa[0] = KPs[r0    ][kb + lt];
            pa[1] = KPs[r0 + 8][kb + lt];
            pa[2] = KPs[r0    ][kb + lt + 4];
            pa[3] = KPs[r0 + 8][kb + lt + 4];
            unsigned vb[8][2];
            #pragma unroll
            for (int ni = 0; ni < 8; ++ni) {
                vb[ni][0] = Vs[kb + lt    ][ni * 8 + lg];
                vb[ni][1] = Vs[kb + lt + 4][ni * 8 + lg];
            }
            #pragma unroll
            for (int ni = 0; ni < 8; ++ni)
                mma_tf32(oacc[ni], pa, vb[ni]);
        }
        __syncthreads();   // before next tile overwrites KPs/Vs
    }

    // ---- finalize: reduce l over the 4 lanes sharing a row, write O ----
    l0 += __shfl_xor_sync(0xffffffffu, l0, 1);
    l0 += __shfl_xor_sync(0xffffffffu, l0, 2);
    l1 += __shfl_xor_sync(0xffffffffu, l1, 1);
    l1 += __shfl_xor_sync(0xffffffffu, l1, 2);
    float inv0 = 1.f / l0, inv1 = 1.f / l1;

    int r0 = qt * 64 + w * 16 + lg;
    #pragma unroll
    for (int ni = 0; ni < 8; ++ni) {
        int c = ni * 8 + 2 * lt;
        float2 o0, o1;
        o0.x = oacc[ni][0] * inv0; o0.y = oacc[ni][1] * inv0;
        o1.x = oacc[ni][2] * inv1; o1.y = oacc[ni][3] * inv1;
        *(float2*)(O + base + (size_t)r0 * DIM + c)       = o0;
        *(float2*)(O + base + (size_t)(r0 + 8) * DIM + c) = o1;
    }
}

// ---------------- launch ------------------------------------------------
extern "C" void kernel_launch(void* const* d_in, const int* in_sizes, int n_in,
                              void* d_out, int out_size)
{
    const float* x     = (const float*)d_in[0];
    const float* wq    = (const float*)d_in[1];
    const float* wk    = (const float*)d_in[2];
    const float* wv    = (const float*)d_in[3];
    const float* wo    = (const float*)d_in[4];
    const float* bo    = (const float*)d_in[5];
    const float* w1    = (const float*)d_in[6];
    const float* b1    = (const float*)d_in[7];
    const float* w2    = (const float*)d_in[8];
    const float* b2    = (const float*)d_in[9];
    const float* gln1  = (const float*)d_in[10];
    const float* bln1  = (const float*)d_in[11];
    const float* gln2  = (const float*)d_in[12];
    const float* bln2  = (const float*)d_in[13];
    float* out = (float*)d_out;

    float *p_h, *p_q, *p_k, *p_v, *p_attn, *p_x1, *p_ff;
    cudaGetSymbolAddress((void**)&p_h,    g_h);
    cudaGetSymbolAddress((void**)&p_q,    g_q);
    cudaGetSymbolAddress((void**)&p_k,    g_k);
    cudaGetSymbolAddress((void**)&p_v,    g_v);
    cudaGetSymbolAddress((void**)&p_attn, g_attn);
    cudaGetSymbolAddress((void**)&p_x1,   g_x1);
    cudaGetSymbolAddress((void**)&p_ff,   g_ff);

    dim3 gD(DIM / 128, MROWS / 128);   // (8, 64)
    dim3 gF(FFD / 128, MROWS / 128);   // (32, 64)

    // 1) h = ln1(x)
    ln_kernel<<<MROWS, 256>>>(x, gln1, bln1, p_h);
    // 2) q,k,v = h @ W{q,k,v}
    gemm_tc<false,false,false><<<gD, 256>>>(p_h, wq, nullptr, nullptr, p_q, MROWS, DIM, DIM);
    gemm_tc<false,false,false><<<gD, 256>>>(p_h, wk, nullptr, nullptr, p_k, MROWS, DIM, DIM);
    gemm_tc<false,false,false><<<gD, 256>>>(p_h, wv, nullptr, nullptr, p_v, MROWS, DIM, DIM);
    // 3) causal attention (tensor cores)
    attn_tc<<<dim3(SEQ / 64, NHEAD, BATCH), 128>>>(p_q, p_k, p_v, p_attn);
    // 4) x1 = x + attn @ wo + bo
    gemm_tc<true,true,false><<<gD, 256>>>(p_attn, wo, bo, x, p_x1, MROWS, DIM, DIM);
    // 5) h = ln2(x1)
    ln_kernel<<<MROWS, 256>>>(p_x1, gln2, bln2, p_h);
    // 6) ff = relu(h @ w1 + b1)
    gemm_tc<true,false,true><<<gF, 256>>>(p_h, w1, b1, nullptr, p_ff, MROWS, FFD, DIM);
    // 7) out = x1 + ff @ w2 + b2
    gemm_tc<true,true,false><<<gD, 256>>>(p_ff, w2, b2, p_x1, out, MROWS, DIM, FFD);
}

// round 5
// speedup vs baseline: 3.6684x; 1.0544x over previous
#include <cuda_runtime.h>
#include <cuda_bf16.h>
#include <cstdio>

// Problem dims (fixed by the reference)
#define BATCH 4
#define SEQ   2048
#define DIM   1024
#define NHEAD 16
#define HDIM  64
#define FFD   4096
#define MROWS (BATCH*SEQ)   // 8192

// ---------------- scratch (static device globals; no runtime alloc) -------
__device__ float g_h   [(size_t)MROWS * DIM];
__device__ float g_q   [(size_t)MROWS * DIM];
__device__ float g_k   [(size_t)MROWS * DIM];
__device__ float g_v   [(size_t)MROWS * DIM];
__device__ float g_attn[(size_t)MROWS * DIM];
__device__ float g_x1  [(size_t)MROWS * DIM];
__device__ float g_ff  [(size_t)MROWS * FFD];
// tf32-rounded weight copies
__device__ float g_wq_r[(size_t)DIM * DIM];
__device__ float g_wk_r[(size_t)DIM * DIM];
__device__ float g_wv_r[(size_t)DIM * DIM];
__device__ float g_wo_r[(size_t)DIM * DIM];
__device__ float g_w1_r[(size_t)DIM * FFD];
__device__ float g_w2_r[(size_t)FFD * DIM];

// ---------------- helpers -------------------------------------------------
__device__ __forceinline__ unsigned f2tf32(float f) {
    unsigned u;
    asm("cvt.rna.tf32.f32 %0, %1;" : "=r"(u) : "f"(f));
    return u;
}
__device__ __forceinline__ float rtf(float f) {    // round-to-tf32 as float
    return __uint_as_float(f2tf32(f));
}

__device__ __forceinline__ void mma_tf32(float* c, const unsigned* a, const unsigned* b) {
    asm volatile(
        "mma.sync.aligned.m16n8k8.row.col.f32.tf32.tf32.f32 "
        "{%0,%1,%2,%3}, {%4,%5,%6,%7}, {%8,%9}, {%0,%1,%2,%3};"
        : "+f"(c[0]), "+f"(c[1]), "+f"(c[2]), "+f"(c[3])
        : "r"(a[0]), "r"(a[1]), "r"(a[2]), "r"(a[3]), "r"(b[0]), "r"(b[1]));
}

__device__ __forceinline__ void cpasync16(void* smem, const void* gmem) {
    unsigned s = (unsigned)__cvta_generic_to_shared(smem);
    asm volatile("cp.async.ca.shared.global [%0], [%1], 16;" :: "r"(s), "l"(gmem));
}
__device__ __forceinline__ void cpcommit() {
    asm volatile("cp.async.commit_group;");
}
template<int N> __device__ __forceinline__ void cpwait() {
    asm volatile("cp.async.wait_group %0;" :: "n"(N));
}

// ---------------- weight pre-round (rna tf32) -----------------------------
__global__ __launch_bounds__(256) void round_kernel(
    const float* __restrict__ X, float* __restrict__ Y, int n4)
{
    int i = blockIdx.x * 256 + threadIdx.x;
    if (i < n4) {
        float4 v = *(const float4*)(X + (size_t)i * 4);
        v.x = rtf(v.x); v.y = rtf(v.y); v.z = rtf(v.z); v.w = rtf(v.w);
        *(float4*)(Y + (size_t)i * 4) = v;
    }
}

// ---------------- layernorm: one row (1024) per block, 256 threads -------
// Output is rna-rounded to tf32 (consumed only as GEMM A operands).
__global__ __launch_bounds__(256) void ln_kernel(
    const float* __restrict__ X, const float* __restrict__ gamma,
    const float* __restrict__ beta, float* __restrict__ Y)
{
    int row = blockIdx.x;
    const float* x = X + (size_t)row * DIM;
    float4 v = *(const float4*)(x + threadIdx.x * 4);
    float s  = v.x + v.y + v.z + v.w;
    float ss = v.x*v.x + v.y*v.y + v.z*v.z + v.w*v.w;

    #pragma unroll
    for (int o = 16; o; o >>= 1) {
        s  += __shfl_xor_sync(0xffffffffu, s, o);
        ss += __shfl_xor_sync(0xffffffffu, ss, o);
    }
    __shared__ float sw[8], ssw[8], bc[2];
    int w = threadIdx.x >> 5, lane = threadIdx.x & 31;
    if (lane == 0) { sw[w] = s; ssw[w] = ss; }
    __syncthreads();
    if (threadIdx.x == 0) {
        float S = 0.f, SS = 0.f;
        #pragma unroll
        for (int i = 0; i < 8; ++i) { S += sw[i]; SS += ssw[i]; }
        float mu  = S * (1.f / DIM);
        float var = SS * (1.f / DIM) - mu * mu;
        bc[0] = mu;
        bc[1] = rsqrtf(var + 1e-5f);
    }
    __syncthreads();
    float mu = bc[0], r = bc[1];
    float4 gv = *(const float4*)(gamma + threadIdx.x * 4);
    float4 bv = *(const float4*)(beta  + threadIdx.x * 4);
    float4 o;
    o.x = rtf((v.x - mu) * r * gv.x + bv.x);
    o.y = rtf((v.y - mu) * r * gv.y + bv.y);
    o.z = rtf((v.z - mu) * r * gv.z + bv.z);
    o.w = rtf((v.w - mu) * r * gv.w + bv.w);
    *(float4*)(Y + (size_t)row * DIM + threadIdx.x * 4) = o;
}

// ---------------- TF32 tensor-core GEMM, 3-stage cp.async pipeline --------
// C[M,N] = A[M,K] @ B[K,N] (+bias)(+res)(relu)(round-out)
// A and B are PRE-ROUNDED to tf32 — mainloop feeds raw bits to the MMA.
// 128x128 block tile, BK=16, 256 threads = 8 warps (2x4), warp tile 64x32.
constexpr int GAP = 20;    // As row stride (floats) — conflict-free frags
constexpr int GBP = 136;   // Bs row stride
constexpr int ASZ = 128 * GAP;   // floats per A stage
constexpr int BSZ = 16 * GBP;    // floats per B stage
constexpr int GEMM_SMEM = 3 * (ASZ + BSZ) * 4;   // 56832 bytes

__device__ __forceinline__ void gemm_load_tile(
    float* As, float* Bs,
    const float* Ablk, const float* Bblk, int k0, int N, int K, int tid)
{
    #pragma unroll
    for (int it = 0; it < 2; ++it) {
        int i = tid + it * 256;
        int r = i >> 2, c4 = (i & 3) << 2;
        cpasync16(As + r * GAP + c4, Ablk + (size_t)r * K + k0 + c4);
    }
    #pragma unroll
    for (int it = 0; it < 2; ++it) {
        int i = tid + it * 256;
        int r = i >> 5, c4 = (i & 31) << 2;
        cpasync16(Bs + r * GBP + c4, Bblk + (size_t)(k0 + r) * N + c4);
    }
}

template<bool HAS_BIAS, bool HAS_RES, bool RELU, bool TF32_OUT>
__global__ __launch_bounds__(256) void gemm_tc(
    const float* __restrict__ A, const float* __restrict__ B,
    const float* __restrict__ bias, const float* __restrict__ Res,
    float* __restrict__ C, int M, int N, int K)
{
    constexpr int BM = 128, BN = 128, BK = 16;
    extern __shared__ float smem[];
    float* AsBase = smem;                 // [3][128][GAP]
    float* BsBase = smem + 3 * ASZ;       // [3][16][GBP]

    int tid  = threadIdx.x;
    int warp = tid >> 5, lane = tid & 31;
    int wm = (warp >> 2) * 64;
    int wn = (warp & 3) * 32;
    int lg = lane >> 2;
    int lt = lane & 3;
    int bm = blockIdx.y, bn = blockIdx.x;

    const float* Ablk = A + (size_t)bm * BM * K;
    const float* Bblk = B + (size_t)bn * BN;

    float acc[4][4][4] = {};

    gemm_load_tile(AsBase, BsBase, Ablk, Bblk, 0, N, K, tid);
    cpcommit();
    gemm_load_tile(AsBase + ASZ, BsBase + BSZ, Ablk, Bblk, BK, N, K, tid);
    cpcommit();

    int T = K / BK;
    int s = 0;
    for (int t = 0; t < T; ++t) {
        cpwait<1>();
        __syncthreads();
        const float* as = AsBase + s * ASZ;
        const float* bs = BsBase + s * BSZ;

        #pragma unroll
        for (int ks = 0; ks < 2; ++ks) {
            int kb = ks * 8;
            unsigned a[4][4], b[4][2];
            #pragma unroll
            for (int mi = 0; mi < 4; ++mi) {
                const float* ar = as + (wm + mi * 16 + lg) * GAP + kb + lt;
                a[mi][0] = __float_as_uint(ar[0]);
                a[mi][1] = __float_as_uint(ar[8 * GAP]);
                a[mi][2] = __float_as_uint(ar[4]);
                a[mi][3] = __float_as_uint(ar[8 * GAP + 4]);
            }
            #pragma unroll
            for (int ni = 0; ni < 4; ++ni) {
                const float* br = bs + (kb + lt) * GBP + wn + ni * 8 + lg;
                b[ni][0] = __float_as_uint(br[0]);
                b[ni][1] = __float_as_uint(br[4 * GBP]);
            }
            #pragma unroll
            for (int mi = 0; mi < 4; ++mi)
                #pragma unroll
                for (int ni = 0; ni < 4; ++ni)
                    mma_tf32(acc[mi][ni], a[mi], b[ni]);
        }
        // prefetch tile t+2 into the stage used at t-1 (safe: single barrier
        // above guarantees all warps finished compute(t-1))
        int nt = t + 2;
        if (nt < T) {
            int sn = nt % 3;
            gemm_load_tile(AsBase + sn * ASZ, BsBase + sn * BSZ,
                           Ablk, Bblk, nt * BK, N, K, tid);
        }
        cpcommit();                      // unconditional: keeps group math valid
        s = (s + 1 == 3) ? 0 : s + 1;
    }

    #pragma unroll
    for (int mi = 0; mi < 4; ++mi) {
        int r0 = bm * BM + wm + mi * 16 + lg;
        #pragma unroll
        for (int ni = 0; ni < 4; ++ni) {
            int c0 = bn * BN + wn + ni * 8 + lt * 2;
            #pragma unroll
            for (int half = 0; half < 2; ++half) {
                int row = r0 + half * 8;
                float2 o;
                o.x = acc[mi][ni][half * 2 + 0];
                o.y = acc[mi][ni][half * 2 + 1];
                if (HAS_BIAS) { o.x += bias[c0]; o.y += bias[c0 + 1]; }
                if (HAS_RES) {
                    float2 rr = *(const float2*)(Res + (size_t)row * N + c0);
                    o.x += rr.x; o.y += rr.y;
                }
                if (RELU) { o.x = fmaxf(o.x, 0.f); o.y = fmaxf(o.y, 0.f); }
                if (TF32_OUT) { o.x = rtf(o.x); o.y = rtf(o.y); }
                *(float2*)(C + (size_t)row * N + c0) = o;
            }
        }
    }
}

// ---------------- tensor-core causal flash attention ----------------------
// Q/K/V arrive pre-rounded to tf32 (QKV GEMM rounds its outputs), so staging
// is a raw copy. Output is rounded (it feeds the WO GEMM as A operand).
__global__ __launch_bounds__(128) void attn_tc(
    const float* __restrict__ Q, const float* __restrict__ Kg,
    const float* __restrict__ Vg, float* __restrict__ O)
{
    __shared__ unsigned KPs[64][68];   // K tile bits, then P tile
    __shared__ unsigned Vs [64][72];   // V tile bits

    int tid = threadIdx.x;
    int w = tid >> 5, lane = tid & 31;
    int lg = lane >> 2, lt = lane & 3;
    int qt = blockIdx.x, h = blockIdx.y, b = blockIdx.z;
    size_t base = ((size_t)b * SEQ) * DIM + h * HDIM;

    // ---- stage Q tile (scaled by 1/8 — exact power of 2, stays tf32) ----
    {
        int f = tid & 15;
        int rsub = tid >> 4;
        #pragma unroll
        for (int pass = 0; pass < 8; ++pass) {
            int row = pass * 8 + rsub;
            float4 v = *(const float4*)(Q + base + (size_t)(qt * 64 + row) * DIM + f * 4);
            uint4 u;
            u.x = __float_as_uint(v.x * 0.125f); u.y = __float_as_uint(v.y * 0.125f);
            u.z = __float_as_uint(v.z * 0.125f); u.w = __float_as_uint(v.w * 0.125f);
            *(uint4*)&KPs[row][f * 4] = u;
        }
    }
    __syncthreads();
    unsigned qa[8][4];
    {
        int r0 = w * 16 + lg;
        #pragma unroll
        for (int ks = 0; ks < 8; ++ks) {
            int kb = ks * 8;
            qa[ks][0] = KPs[r0    ][kb + lt];
            qa[ks][1] = KPs[r0 + 8][kb + lt];
            qa[ks][2] = KPs[r0    ][kb + lt + 4];
            qa[ks][3] = KPs[r0 + 8][kb + lt + 4];
        }
    }
    __syncthreads();

    float m0 = -1e30f, m1 = -1e30f, l0 = 0.f, l1 = 0.f;
    float oacc[8][4] = {};

    for (int kt = 0; kt <= qt; ++kt) {
        // ---- load K,V tiles (raw bit copy, coalesced rows) ----
        {
            int f = tid & 15;
            int rsub = tid >> 4;
            #pragma unroll
            for (int pass = 0; pass < 8; ++pass) {
                int row = pass * 8 + rsub;
                size_t g = base + (size_t)(kt * 64 + row) * DIM + f * 4;
                *(uint4*)&KPs[row][f * 4] = *(const uint4*)(Kg + g);
                *(uint4*)&Vs[row][f * 4]  = *(const uint4*)(Vg + g);
            }
        }
        __syncthreads();

        // ---- S = Q K^T  (16x64 per warp) ----
        float sacc[8][4] = {};
        #pragma unroll
        for (int ks = 0; ks < 8; ++ks) {
            int kb = ks * 8;
            unsigned bf[8][2];
            #pragma unroll
            for (int ni = 0; ni < 8; ++ni) {
                bf[ni][0] = KPs[ni * 8 + lg][kb + lt];
                bf[ni][1] = KPs[ni * 8 + lg][kb + lt + 4];
            }
            #pragma unroll
            for (int ni = 0; ni < 8; ++ni)
                mma_tf32(sacc[ni], qa[ks], bf[ni]);
        }

        // ---- causal mask (diagonal tile only) ----
        if (kt == qt) {
            int rq0 = w * 16 + lg, rq1 = rq0 + 8;
            #pragma unroll
            for (int ni = 0; ni < 8; ++ni) {
                int j0 = ni * 8 + 2 * lt, j1 = j0 + 1;
                if (j0 > rq0) sacc[ni][0] = -1e30f;
                if (j1 > rq0) sacc[ni][1] = -1e30f;
                if (j0 > rq1) sacc[ni][2] = -1e30f;
                if (j1 > rq1) sacc[ni][3] = -1e30f;
            }
        }

        // ---- online softmax ----
        float mx0 = -1e30f, mx1 = -1e30f;
        #pragma unroll
        for (int ni = 0; ni < 8; ++ni) {
            mx0 = fmaxf(mx0, fmaxf(sacc[ni][0], sacc[ni][1]));
            mx1 = fmaxf(mx1, fmaxf(sacc[ni][2], sacc[ni][3]));
        }
        mx0 = fmaxf(mx0, __shfl_xor_sync(0xffffffffu, mx0, 1));
        mx0 = fmaxf(mx0, __shfl_xor_sync(0xffffffffu, mx0, 2));
        mx1 = fmaxf(mx1, __shfl_xor_sync(0xffffffffu, mx1, 1));
        mx1 = fmaxf(mx1, __shfl_xor_sync(0xffffffffu, mx1, 2));
        float m0n = fmaxf(m0, mx0), m1n = fmaxf(m1, mx1);
        float c0 = __expf(m0 - m0n), c1 = __expf(m1 - m1n);
        l0 *= c0; l1 *= c1;
        #pragma unroll
        for (int ni = 0; ni < 8; ++ni) {
            oacc[ni][0] *= c0; oacc[ni][1] *= c0;
            oacc[ni][2] *= c1; oacc[ni][3] *= c1;
        }
        m0 = m0n; m1 = m1n;

        // ---- P = exp(S-m); store into KPs (K no longer needed) ----
        __syncthreads();
        {
            int r0 = w * 16 + lg;
            float ps0 = 0.f, ps1 = 0.f;
            #pragma unroll
            for (int ni = 0; ni < 8; ++ni) {
                float p00 = __expf(sacc[ni][0] - m0n);
                float p01 = __expf(sacc[ni][1] - m0n);
                float p10 = __expf(sacc[ni][2] - m1n);
                float p11 = __expf(sacc[ni][3] - m1n);
                ps0 += p00 + p01; ps1 += p10 + p11;
                uint2 u0; u0.x = f2tf32(p00); u0.y = f2tf32(p01);
                uint2 u1; u1.x = f2tf32(p10); u1.y = f2tf32(p11);
                *(uint2*)&KPs[r0    ][ni * 8 + 2 * lt] = u0;
                *(uint2*)&KPs[r0 + 8][ni * 8 + 2 * lt] = u1;
            }
            l0 += ps0; l1 += ps1;
        }
        __syncwarp();

        // ---- O += P V ----
        #pragma unroll
        for (int ks = 0; ks < 8; ++ks) {
            int kb = ks * 8;
            int r0 = w * 16 + lg;
            unsigned pa[4];
            pa[0] = KPs[r0    ][kb + lt];
            pa[1] = KPs[r0 + 8][kb + lt];
            pa[2] = KPs[r0    ][kb + lt + 4];
            pa[3] = KPs[r0 + 8][kb + lt + 4];
            unsigned vb[8][2];
            #pragma unroll
            for (int ni = 0; ni < 8; ++ni) {
                vb[ni][0] = Vs[kb + lt    ][ni * 8 + lg];
                vb[ni][1] = Vs[kb + lt + 4][ni * 8 + lg];
            }
            #pragma unroll
            for (int ni = 0; ni < 8; ++ni)
                mma_tf32(oacc[ni], pa, vb[ni]);
        }
        __syncthreads();
    }

    // ---- finalize ----
    l0 += __shfl_xor_sync(0xffffffffu, l0, 1);
    l0 += __shfl_xor_sync(0xffffffffu, l0, 2);
    l1 += __shfl_xor_sync(0xffffffffu, l1, 1);
    l1 += __shfl_xor_sync(0xffffffffu, l1, 2);
    float inv0 = 1.f / l0, inv1 = 1.f / l1;

    int r0 = qt * 64 + w * 16 + lg;
    #pragma unroll
    for (int ni = 0; ni < 8; ++ni) {
        int c = ni * 8 + 2 * lt;
        float2 o0, o1;
        o0.x = rtf(oacc[ni][0] * inv0); o0.y = rtf(oacc[ni][1] * inv0);
        o1.x = rtf(oacc[ni][2] * inv1); o1.y = rtf(oacc[ni][3] * inv1);
        *(float2*)(O + base + (size_t)r0 * DIM + c)       = o0;
        *(float2*)(O + base + (size_t)(r0 + 8) * DIM + c) = o1;
    }
}

// ---------------- launch ------------------------------------------------
extern "C" void kernel_launch(void* const* d_in, const int* in_sizes, int n_in,
                              void* d_out, int out_size)
{
    const float* x     = (const float*)d_in[0];
    const float* wq    = (const float*)d_in[1];
    const float* wk    = (const float*)d_in[2];
    const float* wv    = (const float*)d_in[3];
    const float* wo    = (const float*)d_in[4];
    const float* bo    = (const float*)d_in[5];
    const float* w1    = (const float*)d_in[6];
    const float* b1    = (const float*)d_in[7];
    const float* w2    = (const float*)d_in[8];
    const float* b2    = (const float*)d_in[9];
    const float* gln1  = (const float*)d_in[10];
    const float* bln1  = (const float*)d_in[11];
    const float* gln2  = (const float*)d_in[12];
    const float* bln2  = (const float*)d_in[13];
    float* out = (float*)d_out;

    float *p_h, *p_q, *p_k, *p_v, *p_attn, *p_x1, *p_ff;
    float *p_wq, *p_wk, *p_wv, *p_wo, *p_w1, *p_w2;
    cudaGetSymbolAddress((void**)&p_h,    g_h);
    cudaGetSymbolAddress((void**)&p_q,    g_q);
    cudaGetSymbolAddress((void**)&p_k,    g_k);
    cudaGetSymbolAddress((void**)&p_v,    g_v);
    cudaGetSymbolAddress((void**)&p_attn, g_attn);
    cudaGetSymbolAddress((void**)&p_x1,   g_x1);
    cudaGetSymbolAddress((void**)&p_ff,   g_ff);
    cudaGetSymbolAddress((void**)&p_wq,   g_wq_r);
    cudaGetSymbolAddress((void**)&p_wk,   g_wk_r);
    cudaGetSymbolAddress((void**)&p_wv,   g_wv_r);
    cudaGetSymbolAddress((void**)&p_wo,   g_wo_r);
    cudaGetSymbolAddress((void**)&p_w1,   g_w1_r);
    cudaGetSymbolAddress((void**)&p_w2,   g_w2_r);

    // opt-in to >48KB dynamic smem (idempotent host calls; not captured)
    static bool attr_done = false;
    if (!attr_done) {
        cudaFuncSetAttribute(gemm_tc<false,false,false,true>,
            cudaFuncAttributeMaxDynamicSharedMemorySize, GEMM_SMEM);
        cudaFuncSetAttribute(gemm_tc<true,true,false,false>,
            cudaFuncAttributeMaxDynamicSharedMemorySize, GEMM_SMEM);
        cudaFuncSetAttribute(gemm_tc<true,false,true,true>,
            cudaFuncAttributeMaxDynamicSharedMemorySize, GEMM_SMEM);
        attr_done = true;
    }

    dim3 gD(DIM / 128, MROWS / 128);   // (8, 64)
    dim3 gF(FFD / 128, MROWS / 128);   // (32, 64)

    // 0) pre-round weights to tf32 (rna) once per launch (~12us total)
    int nD = DIM * DIM / 4, nF = DIM * FFD / 4;
    round_kernel<<<(nD + 255) / 256, 256>>>(wq, p_wq, nD);
    round_kernel<<<(nD + 255) / 256, 256>>>(wk, p_wk, nD);
    round_kernel<<<(nD + 255) / 256, 256>>>(wv, p_wv, nD);
    round_kernel<<<(nD + 255) / 256, 256>>>(wo, p_wo, nD);
    round_kernel<<<(nF + 255) / 256, 256>>>(w1, p_w1, nF);
    round_kernel<<<(nF + 255) / 256, 256>>>(w2, p_w2, nF);

    // 1) h = ln1(x)  (tf32-rounded output)
    ln_kernel<<<MROWS, 256>>>(x, gln1, bln1, p_h);
    // 2) q,k,v = h @ W{q,k,v}  (tf32-rounded outputs for attention)
    gemm_tc<false,false,false,true><<<gD, 256, GEMM_SMEM>>>(p_h, p_wq, nullptr, nullptr, p_q, MROWS, DIM, DIM);
    gemm_tc<false,false,false,true><<<gD, 256, GEMM_SMEM>>>(p_h, p_wk, nullptr, nullptr, p_k, MROWS, DIM, DIM);
    gemm_tc<false,false,false,true><<<gD, 256, GEMM_SMEM>>>(p_h, p_wv, nullptr, nullptr, p_v, MROWS, DIM, DIM);
    // 3) causal attention (tensor cores; output tf32-rounded)
    attn_tc<<<dim3(SEQ / 64, NHEAD, BATCH), 128>>>(p_q, p_k, p_v, p_attn);
    // 4) x1 = x + attn @ wo + bo   (full fp32 residual)
    gemm_tc<true,true,false,false><<<gD, 256, GEMM_SMEM>>>(p_attn, p_wo, bo, x, p_x1, MROWS, DIM, DIM);
    // 5) h = ln2(x1)  (tf32-rounded output)
    ln_kernel<<<MROWS, 256>>>(p_x1, gln2, bln2, p_h);
    // 6) ff = relu(h @ w1 + b1)  (tf32-rounded output)
    gemm_tc<true,false,true,true><<<gF, 256, GEMM_SMEM>>>(p_h, p_w1, b1, nullptr, p_ff, MROWS, FFD, DIM);
    // 7) out = x1 + ff @ w2 + b2  (full fp32 final output)
    gemm_tc<true,true,false,false><<<gD, 256, GEMM_SMEM>>>(p_ff, p_w2, b2, p_x1, out, MROWS, DIM, FFD);
}